// round 2
// baseline (speedup 1.0000x reference)
#include <cuda_runtime.h>
#include <cstdint>
#include <cstddef>

// ============================================================================
// Arch feature detection: tcgen05 requires the 'a' target (sm_103a / sm_100a).
// On base sm_103 compile passes we fall back to legacy mma.sync (sm_80 ISA).
// ============================================================================
#if defined(__CUDA_ARCH_FEAT_SM103_ALL) || defined(__CUDA_ARCH_FEAT_SM100_ALL) || defined(__CUDA_ARCH_FEAT_SM101_ALL)
#define HAS_TCGEN05 1
#else
#define HAS_TCGEN05 0
#endif

// ============================================================================
// Problem constants
// ============================================================================
#define M_DIM 4096
#define K_DIM 4096
#define N_DIM 11008
#define NW_TOT (N_DIM / 8)
#define GROUP 128

#define TILE_M 128
#define TILE_N 256
#define TILE_K 32                    // 32 tf32 = 128 bytes = one SW128 row
#define M_TILES (M_DIM / TILE_M)     // 32
#define N_TILES (N_DIM / TILE_N)     // 43
#define K_CHUNKS (K_DIM / TILE_K)    // 128

#define A_BLK_BYTES (TILE_M * TILE_K * 4)   // 16384
#define B_BLK_BYTES (TILE_N * TILE_K * 4)   // 32768
#define STAGES 4
#define STAGE_BYTES (A_BLK_BYTES + B_BLK_BYTES)  // 49152
#define GEMM_SMEM_BYTES (1024 + STAGES * STAGE_BYTES + 1024)  // 198656

// idesc for tcgen05.mma kind::tf32: dformat=F32(1)<<4, a=TF32(2)<<7, b=TF32(2)<<10,
// N/8 at [17:23), M/16 at [24:29)
#define MMA_IDESC_TF32 ((1u << 4) | (2u << 7) | (2u << 10) | (32u << 17) | (8u << 24))

// Scratch: pre-tiled, pre-SW128-swizzled tf32 operands.
__device__ __align__(1024) float g_As[(size_t)M_TILES * K_CHUNKS * (TILE_M * TILE_K)];
__device__ __align__(1024) float g_Ws[(size_t)N_TILES * K_CHUNKS * (TILE_N * TILE_K)];

// ============================================================================
// Base-ISA PTX helpers (compile on sm_90+ base targets)
// ============================================================================
__device__ __forceinline__ uint32_t smem_u32(const void* p) {
    uint32_t a;
    asm("{ .reg .u64 t; cvta.to.shared.u64 t, %1; cvt.u32.u64 %0, t; }" : "=r"(a) : "l"(p));
    return a;
}

__device__ __forceinline__ uint32_t sw128(uint32_t byte_off) {
    return byte_off ^ ((byte_off >> 3) & 0x70);
}

__device__ __forceinline__ uint32_t f2tf32(float v) {
    uint32_t r;
    asm("cvt.rna.tf32.f32 %0, %1;" : "=r"(r) : "f"(v));
    return r;
}

#define MBAR_INIT(addr, cnt) \
    asm volatile("mbarrier.init.shared.b64 [%0], %1;" :: "r"(addr), "r"((uint32_t)(cnt)) : "memory")

#define MBAR_EXPECT_TX(addr, bytes) \
    asm volatile("mbarrier.arrive.expect_tx.shared.b64 _, [%0], %1;" :: "r"(addr), "r"((uint32_t)(bytes)) : "memory")

#define MBAR_ARRIVE(addr) \
    asm volatile("mbarrier.arrive.release.cta.shared.b64 _, [%0];" :: "r"(addr) : "memory")

__device__ __forceinline__ void mbar_wait(uint32_t mbar, uint32_t parity) {
    uint32_t done;
    asm volatile(
        "{ .reg .pred p; mbarrier.try_wait.parity.acquire.cta.shared::cta.b64 p, [%1], %2; selp.b32 %0, 1, 0, p; }"
        : "=r"(done) : "r"(mbar), "r"(parity) : "memory");
    if (!done) {
        asm volatile(
            "{ .reg .pred P1;\n"
            "WL_%=: mbarrier.try_wait.parity.acquire.cta.shared::cta.b64 P1, [%0], %1, 0x989680;\n"
            "@P1 bra.uni WD_%=;\n"
            "bra.uni WL_%=;\n"
            "WD_%=: }"
            :: "r"(mbar), "r"(parity) : "memory");
    }
}

__device__ __forceinline__ void bulk_g2s(uint32_t dst_smem, const void* src_gmem,
                                         uint32_t bytes, uint32_t mbar) {
    asm volatile(
        "cp.async.bulk.shared::cluster.global.mbarrier::complete_tx::bytes [%0], [%1], %2, [%3];"
        :: "r"(dst_smem), "l"(src_gmem), "r"(bytes), "r"(mbar) : "memory");
}

// legacy tf32 mma (sm_80 base ISA)
__device__ __forceinline__ void mma_sync_tf32(float* d, const uint32_t* a, const uint32_t* b) {
    asm volatile(
        "mma.sync.aligned.m16n8k8.row.col.f32.tf32.tf32.f32 "
        "{%0, %1, %2, %3}, {%4, %5, %6, %7}, {%8, %9}, {%0, %1, %2, %3};"
        : "+f"(d[0]), "+f"(d[1]), "+f"(d[2]), "+f"(d[3])
        : "r"(a[0]), "r"(a[1]), "r"(a[2]), "r"(a[3]), "r"(b[0]), "r"(b[1]));
}

#if HAS_TCGEN05
// ============================================================================
// sm_103a-only helpers
// ============================================================================
__device__ __forceinline__ uint32_t elect_one() {
    uint32_t p;
    asm volatile("{ .reg .pred p; elect.sync _|p, 0xFFFFFFFF; selp.b32 %0, 1, 0, p; }" : "=r"(p));
    return p;
}

__device__ __forceinline__ uint64_t make_desc_sw128(uint32_t addr) {
    const uint64_t base = (uint64_t(2) << 61) | (uint64_t(1) << 46) |
                          (uint64_t(64) << 32) | (uint64_t(1) << 16);
    return base | ((uint64_t)(addr >> 4) & 0x3FFF);
}

__device__ __forceinline__ void mma_tf32_ss(uint32_t d_tmem, uint64_t a_desc, uint64_t b_desc,
                                            uint32_t idesc, bool acc) {
    uint32_t en = acc ? 1u : 0u;
    asm volatile(
        "{\n\t"
        ".reg .pred p;\n\t"
        "setp.ne.u32 p, %5, 0;\n\t"
        "tcgen05.mma.cta_group::1.kind::tf32 [%0], %1, %2, %3, {%4, %4, %4, %4}, p;\n\t"
        "}"
        :: "r"(d_tmem), "l"(a_desc), "l"(b_desc), "r"(idesc), "r"(0u), "r"(en) : "memory");
}

#define TCGEN05_COMMIT(mbar) \
    asm volatile("tcgen05.commit.cta_group::1.mbarrier::arrive::one.shared::cluster.b64 [%0];" \
                 :: "r"(mbar) : "memory")

__device__ __forceinline__ void tcgen05_ld_x32(uint32_t* r, uint32_t tmem_addr) {
    asm volatile(
        "tcgen05.ld.sync.aligned.32x32b.x32.b32 "
        "{%0, %1, %2, %3, %4, %5, %6, %7, "
        " %8, %9, %10, %11, %12, %13, %14, %15, "
        " %16, %17, %18, %19, %20, %21, %22, %23, "
        " %24, %25, %26, %27, %28, %29, %30, %31}, [%32];"
        : "=r"(r[0]), "=r"(r[1]), "=r"(r[2]), "=r"(r[3]),
          "=r"(r[4]), "=r"(r[5]), "=r"(r[6]), "=r"(r[7]),
          "=r"(r[8]), "=r"(r[9]), "=r"(r[10]), "=r"(r[11]),
          "=r"(r[12]), "=r"(r[13]), "=r"(r[14]), "=r"(r[15]),
          "=r"(r[16]), "=r"(r[17]), "=r"(r[18]), "=r"(r[19]),
          "=r"(r[20]), "=r"(r[21]), "=r"(r[22]), "=r"(r[23]),
          "=r"(r[24]), "=r"(r[25]), "=r"(r[26]), "=r"(r[27]),
          "=r"(r[28]), "=r"(r[29]), "=r"(r[30]), "=r"(r[31])
        : "r"(tmem_addr));
}
#endif  // HAS_TCGEN05

// ============================================================================
// Kernel 1: dequantize int4 weights -> tf32, [N,K] pre-tiled + SW128-swizzled
// ============================================================================
__global__ void __launch_bounds__(256) dequant_kernel(
    const int* __restrict__ qweight,
    const float* __restrict__ scales,
    const int* __restrict__ qzeros
) {
    const int bid = blockIdx.x;
    const int n_tile = bid >> 7;
    const int k_chunk = bid & 127;
    const int k0 = k_chunk * TILE_K;
    const int g = k0 >> 7;

    __shared__ uint32_t tile[TILE_N * TILE_K];

    const int t = threadIdx.x;
    for (int idx = t; idx < TILE_K * 32; idx += 256) {
        const int k_local = idx >> 5;
        const int nw = idx & 31;
        const int n_word = n_tile * 32 + nw;
        const uint32_t qw = (uint32_t)qweight[(size_t)(k0 + k_local) * NW_TOT + n_word];
        const uint32_t qz = (uint32_t)qzeros[(size_t)g * NW_TOT + n_word];
        const int n0 = nw * 8;
        #pragma unroll
        for (int i = 0; i < 8; i++) {
            const float q = (float)((qw >> (4 * i)) & 15u);
            const float z = (float)((qz >> (4 * i)) & 15u);
            const float s = scales[(size_t)g * N_DIM + n_tile * TILE_N + n0 + i];
            const uint32_t wt = f2tf32((q - z) * s);
            const uint32_t off = sw128((uint32_t)((n0 + i) * 128 + k_local * 4));
            tile[off >> 2] = wt;
        }
    }
    __syncthreads();

    float4* dst = reinterpret_cast<float4*>(g_Ws + (size_t)bid * (TILE_N * TILE_K));
    const float4* src = reinterpret_cast<const float4*>(tile);
    for (int i = t; i < (TILE_N * TILE_K) / 4; i += 256) dst[i] = src[i];
}

// ============================================================================
// Kernel 2: activations fp32 -> tf32(RNA), pre-tiled + SW128-swizzled
// ============================================================================
__global__ void __launch_bounds__(256) aconv_kernel(const float* __restrict__ inp) {
    const int bid = blockIdx.x;
    const int m_tile = bid >> 7;
    const int k_chunk = bid & 127;
    const int m0 = m_tile * TILE_M;
    const int k0 = k_chunk * TILE_K;

    __shared__ uint32_t tile[TILE_M * TILE_K];

    const int t = threadIdx.x;
    const int r = t >> 1;
    const int c0 = (t & 1) * 16;
    const float4* src = reinterpret_cast<const float4*>(
        inp + (size_t)(m0 + r) * K_DIM + k0 + c0);
    #pragma unroll
    for (int v = 0; v < 4; v++) {
        const float4 f = src[v];
        const float fv[4] = {f.x, f.y, f.z, f.w};
        #pragma unroll
        for (int e = 0; e < 4; e++) {
            const int c = c0 + v * 4 + e;
            const uint32_t off = sw128((uint32_t)(r * 128 + c * 4));
            tile[off >> 2] = f2tf32(fv[e]);
        }
    }
    __syncthreads();

    float4* dst = reinterpret_cast<float4*>(g_As + (size_t)bid * (TILE_M * TILE_K));
    const float4* s4 = reinterpret_cast<const float4*>(tile);
    for (int i = t; i < (TILE_M * TILE_K) / 4; i += 256) dst[i] = s4[i];
}

// ============================================================================
// Kernel 3: GEMM (128x256 CTA tile, 4-stage bulk-copy pipeline) + fused
// bias + SiLU + mul epilogue. grid = 1376, block = 256.
//   - sm_103a pass: tcgen05 tf32 SS mma, accumulators in TMEM.
//   - base pass: legacy mma.sync m16n8k8 tf32, accumulators in registers.
// ============================================================================
__global__ void __launch_bounds__(256, 1) gemm_kernel(
    const float* __restrict__ bias,
    const float* __restrict__ mul,
    float* __restrict__ out
) {
    extern __shared__ char smem[];
    const uint32_t smem_base = smem_u32(smem);
    const uint32_t data_base = (smem_base + 128 + 1023) & ~1023u;

    const int tid = threadIdx.x;
    const int wid = tid >> 5;
    const int lid = tid & 31;
    const int bid = blockIdx.x;
    const int m_tile = bid & 31;          // m-fast: A slab stays L2-resident
    const int n_tile = bid >> 5;

    const uint32_t FULL0 = smem_base + 8;
    const uint32_t EMPTY0 = smem_base + 40;
    const uint32_t DONE = smem_base + 72;

#if HAS_TCGEN05
    // ------------------------------------------------------------------ tcgen05
    if (wid == 0) {
        asm volatile("tcgen05.alloc.cta_group::1.sync.aligned.shared::cta.b32 [%0], %1;"
                     :: "r"(smem_base), "r"(256u) : "memory");
        asm volatile("tcgen05.relinquish_alloc_permit.cta_group::1.sync.aligned;");
    }
    if (tid == 0) {
        #pragma unroll
        for (int s = 0; s < STAGES; s++) {
            MBAR_INIT(FULL0 + s * 8, 1);
            MBAR_INIT(EMPTY0 + s * 8, 1);
        }
        MBAR_INIT(DONE, 1);
        asm volatile("fence.proxy.async.shared::cta;" ::: "memory");
    }
    __syncthreads();

    uint32_t tmem_base;
    asm volatile("ld.shared.b32 %0, [%1];" : "=r"(tmem_base) : "r"(smem_base));

    if (wid == 0) {
        const uint32_t pred = elect_one();
        const char* a_src = reinterpret_cast<const char*>(g_As) +
                            (size_t)m_tile * K_CHUNKS * A_BLK_BYTES;
        const char* b_src = reinterpret_cast<const char*>(g_Ws) +
                            (size_t)n_tile * K_CHUNKS * B_BLK_BYTES;

        if (pred) {
            #pragma unroll
            for (int j = 0; j < 3; j++) {
                const uint32_t fb = FULL0 + j * 8;
                MBAR_EXPECT_TX(fb, STAGE_BYTES);
                bulk_g2s(data_base + j * STAGE_BYTES, a_src + (size_t)j * A_BLK_BYTES,
                         A_BLK_BYTES, fb);
                bulk_g2s(data_base + j * STAGE_BYTES + A_BLK_BYTES,
                         b_src + (size_t)j * B_BLK_BYTES, B_BLK_BYTES, fb);
            }
        }

        #pragma unroll 1
        for (int it = 0; it < K_CHUNKS; it++) {
            const int s = it & 3;
            mbar_wait(FULL0 + s * 8, (it >> 2) & 1);
            if (pred) {
                const uint64_t a_desc = make_desc_sw128(data_base + s * STAGE_BYTES);
                const uint64_t b_desc = make_desc_sw128(data_base + s * STAGE_BYTES + A_BLK_BYTES);
                #pragma unroll
                for (int ks = 0; ks < 4; ks++)
                    mma_tf32_ss(tmem_base, a_desc + ks * 2, b_desc + ks * 2,
                                MMA_IDESC_TF32, (it | ks) != 0);
                TCGEN05_COMMIT(EMPTY0 + s * 8);
            }
            const int j = it + 3;
            if (j < K_CHUNKS) {
                const int s2 = j & 3;
                if (j >= 4) mbar_wait(EMPTY0 + s2 * 8, ((j - 4) >> 2) & 1);
                if (pred) {
                    const uint32_t fb = FULL0 + s2 * 8;
                    MBAR_EXPECT_TX(fb, STAGE_BYTES);
                    bulk_g2s(data_base + s2 * STAGE_BYTES, a_src + (size_t)j * A_BLK_BYTES,
                             A_BLK_BYTES, fb);
                    bulk_g2s(data_base + s2 * STAGE_BYTES + A_BLK_BYTES,
                             b_src + (size_t)j * B_BLK_BYTES, B_BLK_BYTES, fb);
                }
            }
        }
        if (pred) TCGEN05_COMMIT(DONE);
    }

    // epilogue: 8 warps; warps 0-3 cols 0..127, warps 4-7 cols 128..255
    mbar_wait(DONE, 0);
    asm volatile("tcgen05.fence::after_thread_sync;" ::: "memory");

    const int m = m_tile * TILE_M + (wid & 3) * 32 + lid;
    const int half = wid >> 2;                       // 0 or 1
    const int n_base = n_tile * TILE_N + half * 128;
    const float4* mul4 = reinterpret_cast<const float4*>(mul + (size_t)m * N_DIM + n_base);
    float4* out4 = reinterpret_cast<float4*>(out + (size_t)m * N_DIM + n_base);

    #pragma unroll 1
    for (int cc = 0; cc < 4; cc++) {
        uint32_t d[32];
        tcgen05_ld_x32(d, tmem_base + half * 128 + cc * 32);
        asm volatile("tcgen05.wait::ld.sync.aligned;" ::: "memory");
        #pragma unroll
        for (int v = 0; v < 8; v++) {
            const float4 mv = mul4[cc * 8 + v];
            const float mvf[4] = {mv.x, mv.y, mv.z, mv.w};
            float o[4];
            #pragma unroll
            for (int e = 0; e < 4; e++) {
                const int j = v * 4 + e;
                const float x = __uint_as_float(d[j]) + __ldg(bias + n_base + cc * 32 + j);
                const float sg = 1.0f / (1.0f + __expf(-x));
                o[e] = x * sg * mvf[e];
            }
            out4[cc * 8 + v] = make_float4(o[0], o[1], o[2], o[3]);
        }
    }

    __syncthreads();
    if (wid == 0) {
        asm volatile("tcgen05.dealloc.cta_group::1.sync.aligned.b32 %0, %1;"
                     :: "r"(tmem_base), "r"(256u));
    }

#else
    // ------------------------------------------------------------- mma.sync path
    // 8 warps: 2(M) x 4(N); warp tile 64x64; m16n8k8 tf32.
    if (tid == 0) {
        #pragma unroll
        for (int s = 0; s < STAGES; s++) {
            MBAR_INIT(FULL0 + s * 8, 1);
            MBAR_INIT(EMPTY0 + s * 8, 8);   // one arrive per warp
        }
        asm volatile("fence.proxy.async.shared::cta;" ::: "memory");
    }
    __syncthreads();

    const uint32_t data_off = data_base - smem_base;   // offset of stage 0 in smem[]
    const int m0w = (wid >> 2) * 64;
    const int n0w = (wid & 3) * 64;

    float acc[4][8][4];
    #pragma unroll
    for (int mi = 0; mi < 4; mi++)
        #pragma unroll
        for (int ni = 0; ni < 8; ni++)
            #pragma unroll
            for (int e = 0; e < 4; e++) acc[mi][ni][e] = 0.0f;

    const char* a_src = reinterpret_cast<const char*>(g_As) +
                        (size_t)m_tile * K_CHUNKS * A_BLK_BYTES;
    const char* b_src = reinterpret_cast<const char*>(g_Ws) +
                        (size_t)n_tile * K_CHUNKS * B_BLK_BYTES;

    if (tid == 0) {
        #pragma unroll
        for (int j = 0; j < 3; j++) {
            const uint32_t fb = FULL0 + j * 8;
            MBAR_EXPECT_TX(fb, STAGE_BYTES);
            bulk_g2s(data_base + j * STAGE_BYTES, a_src + (size_t)j * A_BLK_BYTES,
                     A_BLK_BYTES, fb);
            bulk_g2s(data_base + j * STAGE_BYTES + A_BLK_BYTES,
                     b_src + (size_t)j * B_BLK_BYTES, B_BLK_BYTES, fb);
        }
    }

    const int ar = lid >> 2;        // 0..7
    const int ac = lid & 3;         // 0..3

    #pragma unroll 1
    for (int it = 0; it < K_CHUNKS; it++) {
        const int s = it & 3;
        mbar_wait(FULL0 + s * 8, (it >> 2) & 1);

        const uint32_t a_base = data_off + s * STAGE_BYTES;
        const uint32_t b_base = a_base + A_BLK_BYTES;

        #pragma unroll
        for (int ks = 0; ks < 4; ks++) {
            uint32_t afr[4][4];
            #pragma unroll
            for (int mi = 0; mi < 4; mi++) {
                const int r0 = m0w + mi * 16 + ar;
                const int c = ks * 8 + ac;
                afr[mi][0] = *(const uint32_t*)(smem + a_base + sw128(r0 * 128 + c * 4));
                afr[mi][1] = *(const uint32_t*)(smem + a_base + sw128((r0 + 8) * 128 + c * 4));
                afr[mi][2] = *(const uint32_t*)(smem + a_base + sw128(r0 * 128 + (c + 4) * 4));
                afr[mi][3] = *(const uint32_t*)(smem + a_base + sw128((r0 + 8) * 128 + (c + 4) * 4));
            }
            uint32_t bfr[8][2];
            #pragma unroll
            for (int ni = 0; ni < 8; ni++) {
                const int bn = n0w + ni * 8 + ar;        // N row in W block
                const int bk = ks * 8 + ac;              // K col
                bfr[ni][0] = *(const uint32_t*)(smem + b_base + sw128(bn * 128 + bk * 4));
                bfr[ni][1] = *(const uint32_t*)(smem + b_base + sw128(bn * 128 + (bk + 4) * 4));
            }
            #pragma unroll
            for (int mi = 0; mi < 4; mi++)
                #pragma unroll
                for (int ni = 0; ni < 8; ni++)
                    mma_sync_tf32(acc[mi][ni], afr[mi], bfr[ni]);
        }

        if (lid == 0) MBAR_ARRIVE(EMPTY0 + s * 8);

        const int j = it + 3;
        if (j < K_CHUNKS && tid == 0) {
            const int s2 = j & 3;
            if (j >= 4) mbar_wait(EMPTY0 + s2 * 8, ((j - 4) >> 2) & 1);
            const uint32_t fb = FULL0 + s2 * 8;
            MBAR_EXPECT_TX(fb, STAGE_BYTES);
            bulk_g2s(data_base + s2 * STAGE_BYTES, a_src + (size_t)j * A_BLK_BYTES,
                     A_BLK_BYTES, fb);
            bulk_g2s(data_base + s2 * STAGE_BYTES + A_BLK_BYTES,
                     b_src + (size_t)j * B_BLK_BYTES, B_BLK_BYTES, fb);
        }
    }

    // epilogue: registers -> bias + SiLU + mul -> out (float2 stores)
    const int gm0 = m_tile * TILE_M + m0w;
    const int gn0 = n_tile * TILE_N + n0w;
    #pragma unroll
    for (int mi = 0; mi < 4; mi++) {
        #pragma unroll
        for (int hrow = 0; hrow < 2; hrow++) {
            const int m = gm0 + mi * 16 + hrow * 8 + (lid >> 2);
            #pragma unroll
            for (int ni = 0; ni < 8; ni++) {
                const int n = gn0 + ni * 8 + (lid & 3) * 2;
                const float2 mv = *reinterpret_cast<const float2*>(mul + (size_t)m * N_DIM + n);
                float o[2];
                #pragma unroll
                for (int e = 0; e < 2; e++) {
                    const float x = acc[mi][ni][hrow * 2 + e] + __ldg(bias + n + e);
                    const float sg = 1.0f / (1.0f + __expf(-x));
                    o[e] = x * sg * ((e == 0) ? mv.x : mv.y);
                }
                *reinterpret_cast<float2*>(out + (size_t)m * N_DIM + n) = make_float2(o[0], o[1]);
            }
        }
    }
#endif
}

// ============================================================================
// Launch
// ============================================================================
extern "C" void kernel_launch(void* const* d_in, const int* in_sizes, int n_in,
                              void* d_out, int out_size) {
    const float* inp     = (const float*)d_in[0];
    const int*   qweight = (const int*)d_in[1];
    const float* scales  = (const float*)d_in[2];
    const int*   qzeros  = (const int*)d_in[3];
    const float* bias    = (const float*)d_in[4];
    const float* mul     = (const float*)d_in[5];
    float* out = (float*)d_out;

    cudaFuncSetAttribute(gemm_kernel, cudaFuncAttributeMaxDynamicSharedMemorySize,
                         GEMM_SMEM_BYTES);

    dequant_kernel<<<N_TILES * K_CHUNKS, 256>>>(qweight, scales, qzeros);
    aconv_kernel<<<M_TILES * K_CHUNKS, 256>>>(inp);
    gemm_kernel<<<M_TILES * N_TILES, 256, GEMM_SMEM_BYTES>>>(bias, mul, out);
}